// round 16
// baseline (speedup 1.0000x reference)
#include <cuda_runtime.h>
#include <math.h>

#define BB 4
#define CH 64
#define NP 8192
#define KK 16
#define TOT (BB*NP)
#define CAPK 1024
#define SK 10
#define SEEDN 1024
#define EPS_MAIN 0.125f

typedef unsigned long long ull;
typedef unsigned int uint;

#define FMA2(acc, a, b) asm("fma.rn.f32x2 %0, %1, %2, %0;" : "+l"(acc) : "l"(a), "l"(b))
#define MUL2(d, a, b)   asm("mul.rn.f32x2 %0, %1, %2;"    : "=l"(d)   : "l"(a), "l"(b))
#define ADD2(d, a, b)   asm("add.rn.f32x2 %0, %1, %2;"    : "=l"(d)   : "l"(a), "l"(b))

__device__ __forceinline__ ull pack2(float x, float y) {
    ull r; asm("mov.b64 %0, {%1, %2};" : "=l"(r) : "f"(x), "f"(y)); return r;
}
__device__ __forceinline__ float2 unpack2(ull v) {
    float2 r; asm("mov.b64 {%0, %1}, %2;" : "=f"(r.x), "=f"(r.y) : "l"(v)); return r;
}
__device__ __forceinline__ ull skey(float v, int idx) {
    uint b = __float_as_uint(v);
    uint m = ((int)b < 0) ? ~b : (b | 0x80000000u);
    return ((ull)m << 32) | (uint)(~idx);
}

__device__ float g_ft[TOT*CH];
__device__ uint  g_fttf[TOT*CH];
__device__ float g_phit[TOT*CH];
__device__ float g_psit[TOT*CH];
__device__ float g_alphat[TOT*CH];
__device__ float g_sqn[TOT];
__device__ float g_coordst[TOT*3];
__device__ int   g_knn[TOT*KK];
__device__ float g_tauf[TOT];
__device__ int   g_cnt[TOT];
__device__ ull   g_bufk[(size_t)CAPK*TOT];   // row-major [p][e]
__device__ float g_WTd2[CH*CH];
__device__ float g_WTg1[CH*CH];
__device__ float g_WTg2[CH*CH];

__device__ __forceinline__ void dots2(const ull* qa, const ull* qb,
                                      const float* rowf, float& e0, float& e1) {
    const ulonglong2* row = (const ulonglong2*)rowf;
    ull a0,a1,a2,a3,c0,c1,c2,c3;
    {
        ulonglong2 v = row[0];
        MUL2(a0,qa[0],v.x); MUL2(a1,qa[1],v.y);
        MUL2(c0,qb[0],v.x); MUL2(c1,qb[1],v.y);
        ulonglong2 u = row[1];
        MUL2(a2,qa[2],u.x); MUL2(a3,qa[3],u.y);
        MUL2(c2,qb[2],u.x); MUL2(c3,qb[3],u.y);
    }
    #pragma unroll
    for (int j = 2; j < 16; j += 2) {
        ulonglong2 v = row[j];
        FMA2(a0,qa[2*j],v.x);   FMA2(a1,qa[2*j+1],v.y);
        FMA2(c0,qb[2*j],v.x);   FMA2(c1,qb[2*j+1],v.y);
        ulonglong2 u = row[j+1];
        FMA2(a2,qa[2*j+2],u.x); FMA2(a3,qa[2*j+3],u.y);
        FMA2(c2,qb[2*j+2],u.x); FMA2(c3,qb[2*j+3],u.y);
    }
    ADD2(a0,a0,a2); ADD2(a1,a1,a3); ADD2(a0,a0,a1);
    ADD2(c0,c0,c2); ADD2(c1,c1,c3); ADD2(c0,c0,c1);
    float2 sa = unpack2(a0); e0 = sa.x + sa.y;
    float2 sb = unpack2(c0); e1 = sb.x + sb.y;
}

__device__ __forceinline__ void load_q(const float* ft, int q, ull* dst) {
    const float4* p4 = (const float4*)(ft + (size_t)q*CH);
    #pragma unroll
    for (int j = 0; j < 16; j++) {
        float4 v = p4[j];
        dst[2*j]   = pack2(v.x, v.y);
        dst[2*j+1] = pack2(v.z, v.w);
    }
}

__device__ __forceinline__ void mma_tf32(float* d, uint a0, uint a1, uint a2, uint a3,
                                         uint b0, uint b1) {
    asm volatile("mma.sync.aligned.m16n8k8.row.col.f32.tf32.tf32.f32 "
        "{%0,%1,%2,%3}, {%4,%5,%6,%7}, {%8,%9}, {%0,%1,%2,%3};"
        : "+f"(d[0]), "+f"(d[1]), "+f"(d[2]), "+f"(d[3])
        : "r"(a0), "r"(a1), "r"(a2), "r"(a3), "r"(b0), "r"(b1));
}

// ===== Kernel 1: projections + transposes + tf32 pre-convert =====
__global__ void __launch_bounds__(256) proj_kernel(
    const float* __restrict__ feat, const float* __restrict__ coords,
    const float* __restrict__ Wphi, const float* __restrict__ bphi,
    const float* __restrict__ Wpsi, const float* __restrict__ bpsi,
    const float* __restrict__ Wal,  const float* __restrict__ bal,
    const float* __restrict__ Wg1,  const float* __restrict__ Wg2,
    const float* __restrict__ Wd2)
{
    __shared__ float WT[CH*CH];
    __shared__ float fbuf[8][8][CH];
    const int tid = threadIdx.x;
    const int w = tid >> 5, l = tid & 31;

    for (int p = blockIdx.x * 256 + tid; p < TOT; p += gridDim.x * 256) {
        int b = p >> 13, nn = p & (NP - 1);
        const float* cs = coords + b * 3 * NP + nn;
        g_coordst[p*3 + 0] = cs[0];
        g_coordst[p*3 + 1] = cs[NP];
        g_coordst[p*3 + 2] = cs[2*NP];
    }
    if (blockIdx.x == 0) {
        for (int i = tid; i < CH*CH; i += 256) {
            int o = i >> 6, c = i & 63;
            g_WTd2[c*CH + o] = Wd2[i];
            g_WTg1[c*CH + o] = Wg1[i];
            g_WTg2[c*CH + o] = Wg2[i];
        }
    }
    const int pbase = blockIdx.x * 64;
    #pragma unroll
    for (int i = 0; i < 8; i++) {
        int p = pbase + w * 8 + i;
        int b = p >> 13, nn = p & (NP - 1);
        float f0 = feat[(b*CH + 2*l    ) * NP + nn];
        float f1 = feat[(b*CH + 2*l + 1) * NP + nn];
        fbuf[w][i][2*l]     = f0;
        fbuf[w][i][2*l + 1] = f1;
        *(float2*)&g_ft[p*CH + 2*l] = make_float2(f0, f1);
        uint t0, t1;
        asm("cvt.rna.tf32.f32 %0, %1;" : "=r"(t0) : "f"(f0));
        asm("cvt.rna.tf32.f32 %0, %1;" : "=r"(t1) : "f"(f1));
        g_fttf[p*CH + 2*l]     = t0;
        g_fttf[p*CH + 2*l + 1] = t1;
        float sq = f0*f0 + f1*f1;
        #pragma unroll
        for (int off = 16; off; off >>= 1) sq += __shfl_xor_sync(0xffffffffu, sq, off);
        if (l == 0) g_sqn[p] = sq;
    }
    #pragma unroll 1
    for (int mat = 0; mat < 3; mat++) {
        const float* Wg = (mat == 0) ? Wphi : (mat == 1) ? Wpsi : Wal;
        const float* bg = (mat == 0) ? bphi : (mat == 1) ? bpsi : bal;
        float*       og = (mat == 0) ? g_phit : (mat == 1) ? g_psit : g_alphat;
        __syncthreads();
        for (int i = tid; i < CH*CH; i += 256) WT[(i & 63)*CH + (i >> 6)] = Wg[i];
        __syncthreads();
        float bb0 = bg[2*l], bb1 = bg[2*l + 1];
        #pragma unroll 1
        for (int i = 0; i < 8; i++) {
            int p = pbase + w * 8 + i;
            float a0 = bb0, a1 = bb1;
            const float4* fv4 = (const float4*)fbuf[w][i];
            #pragma unroll
            for (int c4 = 0; c4 < 16; c4++) {
                float4 fv = fv4[c4];
                float2 w0 = *(const float2*)&WT[(4*c4 + 0)*CH + 2*l];
                float2 w1 = *(const float2*)&WT[(4*c4 + 1)*CH + 2*l];
                float2 w2 = *(const float2*)&WT[(4*c4 + 2)*CH + 2*l];
                float2 w3 = *(const float2*)&WT[(4*c4 + 3)*CH + 2*l];
                a0 = fmaf(w0.x, fv.x, a0); a1 = fmaf(w0.y, fv.x, a1);
                a0 = fmaf(w1.x, fv.y, a0); a1 = fmaf(w1.y, fv.y, a1);
                a0 = fmaf(w2.x, fv.z, a0); a1 = fmaf(w2.y, fv.z, a1);
                a0 = fmaf(w3.x, fv.w, a0); a1 = fmaf(w3.y, fv.w, a1);
            }
            *(float2*)&og[p*CH + 2*l] = make_float2(a0, a1);
        }
    }
}

// ===== Kernel 2a: seed — exact fp32 16th-best over cands 0..SEEDN-1; zero cnt ====
__global__ void __launch_bounds__(128) seed_kernel() {
    __shared__ float sh[128*68];
    __shared__ float sqs[128];
    const int tid = threadIdx.x;
    const int b = blockIdx.x >> 5;
    const int qbase = (blockIdx.x & 31) * 256;
    const float* ft = g_ft + (size_t)b * NP * CH;

    ull qa[32], qb[32];
    load_q(ft, qbase + tid, qa);
    load_q(ft, qbase + tid + 128, qb);

    float bd0[16], bd1[16];
    #pragma unroll
    for (int t = 0; t < 16; t++) { bd0[t] = -3.0e38f; bd1[t] = -3.0e38f; }
    float thr0 = -3.0e38f, thr1 = -3.0e38f;
    int mp0 = 0, mp1 = 0;

    #pragma unroll 1
    for (int tb = 0; tb < SEEDN; tb += 128) {
        __syncthreads();
        const float4* src = (const float4*)(ft + (size_t)tb * CH);
        #pragma unroll
        for (int it = 0; it < 16; it++) {
            int i4 = tid + it * 128;
            int mi = i4 >> 4, c4 = i4 & 15;
            *(float4*)&sh[mi*68 + 4*c4] = src[i4];
        }
        sqs[tid] = g_sqn[b*NP + tb + tid];
        __syncthreads();

        #pragma unroll 1
        for (int mi = 0; mi < 128; mi++) {
            float e0, e1;
            dots2(qa, qb, &sh[mi*68], e0, e1);
            float sq = sqs[mi];
            float v0 = fmaf(2.f, e0, -sq);
            float v1 = fmaf(2.f, e1, -sq);
            if (v0 > thr0) {
                #pragma unroll
                for (int t = 0; t < 16; t++) if (t == mp0) bd0[t] = v0;
                float mn = bd0[0]; int mpos = 0;
                #pragma unroll
                for (int t = 1; t < 16; t++) if (bd0[t] < mn) { mn = bd0[t]; mpos = t; }
                thr0 = mn; mp0 = mpos;
            }
            if (v1 > thr1) {
                #pragma unroll
                for (int t = 0; t < 16; t++) if (t == mp1) bd1[t] = v1;
                float mn = bd1[0]; int mpos = 0;
                #pragma unroll
                for (int t = 1; t < 16; t++) if (bd1[t] < mn) { mn = bd1[t]; mpos = t; }
                thr1 = mn; mp1 = mpos;
            }
        }
    }
    int p0 = b*NP + qbase + tid, p1 = p0 + 128;
    g_tauf[p0] = thr0; g_cnt[p0] = 0;
    g_tauf[p1] = thr1; g_cnt[p1] = 0;
}

// ===== Kernel 2b: tf32 MMA distance tiles + threshold append (symmetric) =====
#define PUSH(KEY, TGT) do { \
    if (sp < SK) { stk[sp*256 + tid] = (KEY); stg[sp*256 + tid] = (TGT); sp++; } \
    else { int _pos = atomicAdd(&g_cnt[TGT], 1); \
           if (_pos < CAPK) g_bufk[(size_t)(TGT)*CAPK + _pos] = (KEY); } \
} while (0)

__global__ void __launch_bounds__(256, 2) mma_knn_kernel() {
    extern __shared__ char dynsm[];
    uint*  smi = (uint*)dynsm;
    uint*  smj = smi + 128*68;
    ull*   stk = (ull*)(smj + 128*68);
    int*   stg = (int*)(stk + SK*256);
    float* sqi = (float*)(stg + SK*256);
    float* sqj = sqi + 128;
    float* tti = sqj + 128;
    float* ttj = tti + 128;

    const int tid = threadIdx.x;
    int tb = blockIdx.x;
    const int b = tb / 2080;
    int r = tb - b * 2080;
    int ci = 0;
    while (r >= 64 - ci) { r -= 64 - ci; ci++; }
    const int cj = ci + r;
    const bool offd = (ci != cj);
    const int qch = ci * 128, cch = cj * 128;
    const int bNP = b * NP;
    const uint* ftf = g_fttf + (size_t)bNP * CH;

    #pragma unroll
    for (int it = 0; it < 8; it++) {
        int i4 = tid + it * 256;
        int row = i4 >> 4, c4 = i4 & 15;
        *(uint4*)&smi[row*68 + c4*4] = *(const uint4*)&ftf[(size_t)(qch + row)*CH + c4*4];
        *(uint4*)&smj[row*68 + c4*4] = *(const uint4*)&ftf[(size_t)(cch + row)*CH + c4*4];
    }
    if (tid < 128) {
        sqi[tid] = g_sqn[bNP + qch + tid];
        sqj[tid] = g_sqn[bNP + cch + tid];
        tti[tid] = g_tauf[bNP + qch + tid] - EPS_MAIN;
        ttj[tid] = g_tauf[bNP + cch + tid] - EPS_MAIN;
    }
    __syncthreads();

    const int w = tid >> 5, t = tid & 31, ty = t >> 2, tx = t & 3;
    float acc[64];
    #pragma unroll
    for (int z = 0; z < 64; z++) acc[z] = 0.f;
    const int arow0 = (w*16 + ty)*68, arow1 = arow0 + 8*68;

    #pragma unroll
    for (int ks = 0; ks < 8; ks++) {
        int ko = ks*8 + tx;
        uint a0 = smi[arow0 + ko],     a1 = smi[arow1 + ko];
        uint a2 = smi[arow0 + ko + 4], a3 = smi[arow1 + ko + 4];
        #pragma unroll
        for (int nt = 0; nt < 16; nt++) {
            int boff = (nt*8 + ty)*68 + ko;
            mma_tf32(acc + nt*4, a0, a1, a2, a3, smj[boff], smj[boff + 4]);
        }
    }

    int sp = 0;
    const int lr0 = w*16 + ty, lr1 = lr0 + 8;
    const float sq0 = sqi[lr0], sq1 = sqi[lr1];
    const float tt0 = tti[lr0], tt1 = tti[lr1];
    const int pq0 = bNP + qch + lr0, pq1 = pq0 + 8;
    const int gq0 = qch + lr0, gq1 = gq0 + 8;

    #pragma unroll
    for (int nt = 0; nt < 16; nt++) {
        int lc0 = nt*8 + tx*2, lc1 = lc0 + 1;
        float sj0 = sqj[lc0], sj1 = sqj[lc1];
        int gm0 = cch + lc0, gm1 = cch + lc1;
        float a0v = acc[4*nt], a1v = acc[4*nt+1], a2v = acc[4*nt+2], a3v = acc[4*nt+3];
        float s;
        s = fmaf(2.f, a0v, -sj0); if (s >= tt0) PUSH(skey(s, gm0), pq0);
        s = fmaf(2.f, a1v, -sj1); if (s >= tt0) PUSH(skey(s, gm1), pq0);
        s = fmaf(2.f, a2v, -sj0); if (s >= tt1) PUSH(skey(s, gm0), pq1);
        s = fmaf(2.f, a3v, -sj1); if (s >= tt1) PUSH(skey(s, gm1), pq1);
        if (offd) {
            float tj0 = ttj[lc0], tj1 = ttj[lc1];
            int pm0 = bNP + gm0, pm1 = bNP + gm1;
            s = fmaf(2.f, a0v, -sq0); if (s >= tj0) PUSH(skey(s, gq0), pm0);
            s = fmaf(2.f, a1v, -sq0); if (s >= tj1) PUSH(skey(s, gq0), pm1);
            s = fmaf(2.f, a2v, -sq1); if (s >= tj0) PUSH(skey(s, gq1), pm0);
            s = fmaf(2.f, a3v, -sq1); if (s >= tj1) PUSH(skey(s, gq1), pm1);
        }
    }

    {
        int posv[SK];
        #pragma unroll
        for (int k = 0; k < SK; k++)
            posv[k] = (k < sp) ? atomicAdd(&g_cnt[stg[k*256 + tid]], 1) : 0;
        #pragma unroll
        for (int k = 0; k < SK; k++) if (k < sp) {
            int pos = posv[k];
            if (pos < CAPK) g_bufk[(size_t)stg[k*256 + tid]*CAPK + pos] = stk[k*256 + tid];
        }
    }
}

// ===== Kernel 2c: select — warp/query, cooperative coalesced rescore =====
// Warp rescores each entry cooperatively: coalesced float2 row load + butterfly
// reduce; all lanes maintain an identical exact top-16 (uniform inserts).
__global__ void __launch_bounds__(256) select_kernel() {
    const int lane = threadIdx.x & 31;
    const int p = blockIdx.x * 8 + (threadIdx.x >> 5);
    const int b = p >> 13;
    const int bNP = b * NP;
    int n = g_cnt[p]; if (n > CAPK) n = CAPK;

    const ull* row = g_bufk + (size_t)p * CAPK;
    const float2 q2 = *(const float2*)(g_ft + (size_t)p * CH + 2*lane);

    ull bk[16];
    #pragma unroll
    for (int t = 0; t < 16; t++) bk[t] = 0ull;
    ull thrk = 0ull; int mp = 0;

    #pragma unroll 1
    for (int e = 0; e < n; e += 2) {
        const bool hasB = (e + 1 < n);
        ull kA = row[e];
        ull kB = hasB ? row[e+1] : kA;
        int mA = (int)~(uint)kA;
        int mB = (int)~(uint)kB;
        float2 cA = *(const float2*)(g_ft + (size_t)(bNP + mA)*CH + 2*lane);
        float2 cB = *(const float2*)(g_ft + (size_t)(bNP + mB)*CH + 2*lane);
        float sA = fmaf(q2.x, cA.x, q2.y * cA.y);
        float sB = fmaf(q2.x, cB.x, q2.y * cB.y);
        #pragma unroll
        for (int off = 16; off; off >>= 1) {
            sA += __shfl_xor_sync(0xffffffffu, sA, off);
            sB += __shfl_xor_sync(0xffffffffu, sB, off);
        }
        float vA = fmaf(2.f, sA, -g_sqn[bNP + mA]);
        ull k2 = skey(vA, mA);
        if (k2 > thrk) {
            #pragma unroll
            for (int t = 0; t < 16; t++) if (t == mp) bk[t] = k2;
            ull mn = bk[0]; int mpos = 0;
            #pragma unroll
            for (int t = 1; t < 16; t++) if (bk[t] < mn) { mn = bk[t]; mpos = t; }
            thrk = mn; mp = mpos;
        }
        if (hasB) {
            float vB = fmaf(2.f, sB, -g_sqn[bNP + mB]);
            ull k3 = skey(vB, mB);
            if (k3 > thrk) {
                #pragma unroll
                for (int t = 0; t < 16; t++) if (t == mp) bk[t] = k3;
                ull mn = bk[0]; int mpos = 0;
                #pragma unroll
                for (int t = 1; t < 16; t++) if (bk[t] < mn) { mn = bk[t]; mpos = t; }
                thrk = mn; mp = mpos;
            }
        }
    }

    if (lane == 0) {
        int* dst = g_knn + (size_t)p * KK;
        #pragma unroll
        for (int t = 0; t < 16; t++) dst[t] = (int)~(uint)bk[t];
    }
}

// ===== Kernel 3: per-neighbor MLP + softmax =====
__global__ void __launch_bounds__(128) agg_kernel(
    const float* __restrict__ Wd1, const float* __restrict__ bd1,
    const float* __restrict__ bd2, const float* __restrict__ bg1,
    const float* __restrict__ bg2, float* __restrict__ out)
{
    __shared__ float bufA[4][CH * 20];
    __shared__ float bufB[4][CH * 20];
    __shared__ float cds[4][48];
    __shared__ int   idxs[4][16];

    const int w = threadIdx.x >> 5, l = threadIdx.x & 31;
    const int r0 = 2 * l, r1 = 2 * l + 1;

    const float w00 = Wd1[r0*3+0], w01 = Wd1[r0*3+1], w02 = Wd1[r0*3+2];
    const float w10 = Wd1[r1*3+0], w11 = Wd1[r1*3+1], w12 = Wd1[r1*3+2];
    const float bd1_0 = bd1[r0], bd1_1 = bd1[r1];
    const float bd2_0 = bd2[r0], bd2_1 = bd2[r1];
    const float bg1_0 = bg1[r0], bg1_1 = bg1[r1];
    const float bg2_0 = bg2[r0], bg2_1 = bg2[r1];

    #pragma unroll 1
    for (int i = 0; i < 8; i++) {
        const int p = (blockIdx.x * 4 + w) * 8 + i;
        const int b = p >> 13, n = p & (NP - 1);

        if (l < 16) {
            int m = g_knn[p * KK + l];
            idxs[w][l] = m;
            const float* cn = g_coordst + p * 3;
            const float* cm = g_coordst + (b * NP + m) * 3;
            cds[w][l]      = cn[0] - cm[0];
            cds[w][16 + l] = cn[1] - cm[1];
            cds[w][32 + l] = cn[2] - cm[2];
        }
        __syncwarp();

        #pragma unroll
        for (int k = 0; k < 16; k++) {
            float c0 = cds[w][k], c1 = cds[w][16 + k], c2 = cds[w][32 + k];
            float h0 = fmaxf(fmaf(w02, c2, fmaf(w01, c1, fmaf(w00, c0, bd1_0))), 0.f);
            float h1 = fmaxf(fmaf(w12, c2, fmaf(w11, c1, fmaf(w10, c0, bd1_1))), 0.f);
            bufA[w][r0*20 + k] = h0;
            bufA[w][r1*20 + k] = h1;
        }
        __syncwarp();

        ull D0[8], D1[8];
        {
            ull b0 = pack2(bd2_0, bd2_0), b1 = pack2(bd2_1, bd2_1);
            #pragma unroll
            for (int jj = 0; jj < 8; jj++) { D0[jj] = b0; D1[jj] = b1; }
        }
        #pragma unroll 4
        for (int c = 0; c < CH; c++) {
            float2 wv = *(const float2*)&g_WTd2[c*CH + r0];
            ull wx = pack2(wv.x, wv.x), wy = pack2(wv.y, wv.y);
            const ulonglong2* hr = (const ulonglong2*)&bufA[w][c*20];
            #pragma unroll
            for (int jj = 0; jj < 4; jj++) {
                ulonglong2 h2 = hr[jj];
                FMA2(D0[2*jj], wx, h2.x); FMA2(D0[2*jj+1], wx, h2.y);
                FMA2(D1[2*jj], wy, h2.x); FMA2(D1[2*jj+1], wy, h2.y);
            }
        }
        float d0[16], d1[16];
        #pragma unroll
        for (int jj = 0; jj < 8; jj++) {
            float2 u = unpack2(D0[jj]); d0[2*jj] = u.x; d0[2*jj+1] = u.y;
            float2 v = unpack2(D1[jj]); d1[2*jj] = v.x; d1[2*jj+1] = v.y;
        }
        __syncwarp();

        {
            float2 ph = *(const float2*)&g_phit[p*CH + r0];
            #pragma unroll
            for (int k = 0; k < 16; k++) {
                int m = idxs[w][k];
                float2 ps = *(const float2*)&g_psit[(size_t)(b*NP + m)*CH + r0];
                bufA[w][r0*20 + k] = ph.x - ps.x + d0[k];
                bufA[w][r1*20 + k] = ph.y - ps.y + d1[k];
            }
        }
        __syncwarp();

        {
            ull G0[8], G1[8];
            {
                ull b0 = pack2(bg1_0, bg1_0), b1 = pack2(bg1_1, bg1_1);
                #pragma unroll
                for (int jj = 0; jj < 8; jj++) { G0[jj] = b0; G1[jj] = b1; }
            }
            #pragma unroll 4
            for (int c = 0; c < CH; c++) {
                float2 wv = *(const float2*)&g_WTg1[c*CH + r0];
                ull wx = pack2(wv.x, wv.x), wy = pack2(wv.y, wv.y);
                const ulonglong2* xr = (const ulonglong2*)&bufA[w][c*20];
                #pragma unroll
                for (int jj = 0; jj < 4; jj++) {
                    ulonglong2 x2 = xr[jj];
                    FMA2(G0[2*jj], wx, x2.x); FMA2(G0[2*jj+1], wx, x2.y);
                    FMA2(G1[2*jj], wy, x2.x); FMA2(G1[2*jj+1], wy, x2.y);
                }
            }
            #pragma unroll
            for (int jj = 0; jj < 8; jj++) {
                float2 u = unpack2(G0[jj]);
                bufB[w][r0*20 + 2*jj]     = fmaxf(u.x, 0.f);
                bufB[w][r0*20 + 2*jj + 1] = fmaxf(u.y, 0.f);
                float2 v = unpack2(G1[jj]);
                bufB[w][r1*20 + 2*jj]     = fmaxf(v.x, 0.f);
                bufB[w][r1*20 + 2*jj + 1] = fmaxf(v.y, 0.f);
            }
        }
        __syncwarp();

        float gm0[16], gm1[16];
        {
            ull M0[8], M1[8];
            {
                ull b0 = pack2(bg2_0, bg2_0), b1 = pack2(bg2_1, bg2_1);
                #pragma unroll
                for (int jj = 0; jj < 8; jj++) { M0[jj] = b0; M1[jj] = b1; }
            }
            #pragma unroll 4
            for (int c = 0; c < CH; c++) {
                float2 wv = *(const float2*)&g_WTg2[c*CH + r0];
                ull wx = pack2(wv.x, wv.x), wy = pack2(wv.y, wv.y);
                const ulonglong2* gr = (const ulonglong2*)&bufB[w][c*20];
                #pragma unroll
                for (int jj = 0; jj < 4; jj++) {
                    ulonglong2 g2 = gr[jj];
                    FMA2(M0[2*jj], wx, g2.x); FMA2(M0[2*jj+1], wx, g2.y);
                    FMA2(M1[2*jj], wy, g2.x); FMA2(M1[2*jj+1], wy, g2.y);
                }
            }
            #pragma unroll
            for (int jj = 0; jj < 8; jj++) {
                float2 u = unpack2(M0[jj]); gm0[2*jj] = u.x; gm0[2*jj+1] = u.y;
                float2 v = unpack2(M1[jj]); gm1[2*jj] = v.x; gm1[2*jj+1] = v.y;
            }
        }

        {
            float mx0 = gm0[0], mx1 = gm1[0];
            #pragma unroll
            for (int k = 1; k < 16; k++) { mx0 = fmaxf(mx0, gm0[k]); mx1 = fmaxf(mx1, gm1[k]); }
            float s0 = 0.f, s1 = 0.f;
            #pragma unroll
            for (int k = 0; k < 16; k++) {
                gm0[k] = __expf(gm0[k] - mx0); s0 += gm0[k];
                gm1[k] = __expf(gm1[k] - mx1); s1 += gm1[k];
            }
            float2 al = *(const float2*)&g_alphat[p*CH + r0];
            float acc0 = 0.f, acc1 = 0.f;
            #pragma unroll
            for (int k = 0; k < 16; k++) {
                acc0 = fmaf(gm0[k], al.x + d0[k], acc0);
                acc1 = fmaf(gm1[k], al.y + d1[k], acc1);
            }
            out[(size_t)b*CH*NP + (size_t)r0*NP + n] = acc0 / s0;
            out[(size_t)b*CH*NP + (size_t)r1*NP + n] = acc1 / s1;
        }
        __syncwarp();
    }
}

extern "C" void kernel_launch(void* const* d_in, const int* in_sizes, int n_in,
                              void* d_out, int out_size) {
    const float* features = (const float*)d_in[0];
    const float* coords   = (const float*)d_in[1];

    const int mma_smem = 2*128*68*4 + SK*256*8 + SK*256*4 + 4*128*4;  // 102400 B
    static int attr_done = 0;
    if (!attr_done) {
        cudaFuncSetAttribute(mma_knn_kernel, cudaFuncAttributeMaxDynamicSharedMemorySize, mma_smem);
        attr_done = 1;
    }

    proj_kernel<<<512, 256>>>(features, coords,
        (const float*)d_in[2], (const float*)d_in[3],
        (const float*)d_in[4], (const float*)d_in[5],
        (const float*)d_in[6], (const float*)d_in[7],
        (const float*)d_in[8], (const float*)d_in[10],
        (const float*)d_in[14]);
    seed_kernel<<<128, 128>>>();
    mma_knn_kernel<<<4*2080, 256, mma_smem>>>();
    select_kernel<<<TOT/8, 256>>>();
    agg_kernel<<<1024, 128>>>(
        (const float*)d_in[12], (const float*)d_in[13],
        (const float*)d_in[15], (const float*)d_in[9],
        (const float*)d_in[11], (float*)d_out);
}

// round 17
// speedup vs baseline: 1.1711x; 1.1711x over previous
#include <cuda_runtime.h>
#include <math.h>

#define BB 4
#define CH 64
#define NP 8192
#define KK 16
#define TOT (BB*NP)
#define CAPK 1024
#define SK 10
#define SEEDN 1024
#define EPS_MAIN 0.125f
#define EPS_SEL 0.15f

typedef unsigned long long ull;
typedef unsigned int uint;

#define FMA2(acc, a, b) asm("fma.rn.f32x2 %0, %1, %2, %0;" : "+l"(acc) : "l"(a), "l"(b))
#define MUL2(d, a, b)   asm("mul.rn.f32x2 %0, %1, %2;"    : "=l"(d)   : "l"(a), "l"(b))
#define ADD2(d, a, b)   asm("add.rn.f32x2 %0, %1, %2;"    : "=l"(d)   : "l"(a), "l"(b))

__device__ __forceinline__ ull pack2(float x, float y) {
    ull r; asm("mov.b64 %0, {%1, %2};" : "=l"(r) : "f"(x), "f"(y)); return r;
}
__device__ __forceinline__ float2 unpack2(ull v) {
    float2 r; asm("mov.b64 {%0, %1}, %2;" : "=f"(r.x), "=f"(r.y) : "l"(v)); return r;
}
__device__ __forceinline__ ull skey(float v, int idx) {
    uint b = __float_as_uint(v);
    uint m = ((int)b < 0) ? ~b : (b | 0x80000000u);
    return ((ull)m << 32) | (uint)(~idx);
}
__device__ __forceinline__ float keyval(ull k) {
    uint m = (uint)(k >> 32);
    uint bits = (m & 0x80000000u) ? (m ^ 0x80000000u) : ~m;
    return __uint_as_float(bits);
}

__device__ float g_ft[TOT*CH];
__device__ uint  g_fttf[TOT*CH];
__device__ float g_phit[TOT*CH];
__device__ float g_psit[TOT*CH];
__device__ float g_alphat[TOT*CH];
__device__ float g_sqn[TOT];
__device__ float g_coordst[TOT*3];
__device__ int   g_knn[TOT*KK];
__device__ float g_tauf[TOT];
__device__ int   g_cnt[TOT];
__device__ ull   g_bufk[(size_t)CAPK*TOT];   // row-major [p][e]
__device__ float g_WTd2[CH*CH];
__device__ float g_WTg1[CH*CH];
__device__ float g_WTg2[CH*CH];

__device__ __forceinline__ void dots2(const ull* qa, const ull* qb,
                                      const float* rowf, float& e0, float& e1) {
    const ulonglong2* row = (const ulonglong2*)rowf;
    ull a0,a1,a2,a3,c0,c1,c2,c3;
    {
        ulonglong2 v = row[0];
        MUL2(a0,qa[0],v.x); MUL2(a1,qa[1],v.y);
        MUL2(c0,qb[0],v.x); MUL2(c1,qb[1],v.y);
        ulonglong2 u = row[1];
        MUL2(a2,qa[2],u.x); MUL2(a3,qa[3],u.y);
        MUL2(c2,qb[2],u.x); MUL2(c3,qb[3],u.y);
    }
    #pragma unroll
    for (int j = 2; j < 16; j += 2) {
        ulonglong2 v = row[j];
        FMA2(a0,qa[2*j],v.x);   FMA2(a1,qa[2*j+1],v.y);
        FMA2(c0,qb[2*j],v.x);   FMA2(c1,qb[2*j+1],v.y);
        ulonglong2 u = row[j+1];
        FMA2(a2,qa[2*j+2],u.x); FMA2(a3,qa[2*j+3],u.y);
        FMA2(c2,qb[2*j+2],u.x); FMA2(c3,qb[2*j+3],u.y);
    }
    ADD2(a0,a0,a2); ADD2(a1,a1,a3); ADD2(a0,a0,a1);
    ADD2(c0,c0,c2); ADD2(c1,c1,c3); ADD2(c0,c0,c1);
    float2 sa = unpack2(a0); e0 = sa.x + sa.y;
    float2 sb = unpack2(c0); e1 = sb.x + sb.y;
}

__device__ __forceinline__ void load_q(const float* ft, int q, ull* dst) {
    const float4* p4 = (const float4*)(ft + (size_t)q*CH);
    #pragma unroll
    for (int j = 0; j < 16; j++) {
        float4 v = p4[j];
        dst[2*j]   = pack2(v.x, v.y);
        dst[2*j+1] = pack2(v.z, v.w);
    }
}

__device__ __forceinline__ void mma_tf32(float* d, uint a0, uint a1, uint a2, uint a3,
                                         uint b0, uint b1) {
    asm volatile("mma.sync.aligned.m16n8k8.row.col.f32.tf32.tf32.f32 "
        "{%0,%1,%2,%3}, {%4,%5,%6,%7}, {%8,%9}, {%0,%1,%2,%3};"
        : "+f"(d[0]), "+f"(d[1]), "+f"(d[2]), "+f"(d[3])
        : "r"(a0), "r"(a1), "r"(a2), "r"(a3), "r"(b0), "r"(b1));
}

// ===== Kernel 1: projections + transposes + tf32 pre-convert =====
__global__ void __launch_bounds__(256) proj_kernel(
    const float* __restrict__ feat, const float* __restrict__ coords,
    const float* __restrict__ Wphi, const float* __restrict__ bphi,
    const float* __restrict__ Wpsi, const float* __restrict__ bpsi,
    const float* __restrict__ Wal,  const float* __restrict__ bal,
    const float* __restrict__ Wg1,  const float* __restrict__ Wg2,
    const float* __restrict__ Wd2)
{
    __shared__ float WT[CH*CH];
    __shared__ float fbuf[8][8][CH];
    const int tid = threadIdx.x;
    const int w = tid >> 5, l = tid & 31;

    for (int p = blockIdx.x * 256 + tid; p < TOT; p += gridDim.x * 256) {
        int b = p >> 13, nn = p & (NP - 1);
        const float* cs = coords + b * 3 * NP + nn;
        g_coordst[p*3 + 0] = cs[0];
        g_coordst[p*3 + 1] = cs[NP];
        g_coordst[p*3 + 2] = cs[2*NP];
    }
    if (blockIdx.x == 0) {
        for (int i = tid; i < CH*CH; i += 256) {
            int o = i >> 6, c = i & 63;
            g_WTd2[c*CH + o] = Wd2[i];
            g_WTg1[c*CH + o] = Wg1[i];
            g_WTg2[c*CH + o] = Wg2[i];
        }
    }
    const int pbase = blockIdx.x * 64;
    #pragma unroll
    for (int i = 0; i < 8; i++) {
        int p = pbase + w * 8 + i;
        int b = p >> 13, nn = p & (NP - 1);
        float f0 = feat[(b*CH + 2*l    ) * NP + nn];
        float f1 = feat[(b*CH + 2*l + 1) * NP + nn];
        fbuf[w][i][2*l]     = f0;
        fbuf[w][i][2*l + 1] = f1;
        *(float2*)&g_ft[p*CH + 2*l] = make_float2(f0, f1);
        uint t0, t1;
        asm("cvt.rna.tf32.f32 %0, %1;" : "=r"(t0) : "f"(f0));
        asm("cvt.rna.tf32.f32 %0, %1;" : "=r"(t1) : "f"(f1));
        g_fttf[p*CH + 2*l]     = t0;
        g_fttf[p*CH + 2*l + 1] = t1;
        float sq = f0*f0 + f1*f1;
        #pragma unroll
        for (int off = 16; off; off >>= 1) sq += __shfl_xor_sync(0xffffffffu, sq, off);
        if (l == 0) g_sqn[p] = sq;
    }
    #pragma unroll 1
    for (int mat = 0; mat < 3; mat++) {
        const float* Wg = (mat == 0) ? Wphi : (mat == 1) ? Wpsi : Wal;
        const float* bg = (mat == 0) ? bphi : (mat == 1) ? bpsi : bal;
        float*       og = (mat == 0) ? g_phit : (mat == 1) ? g_psit : g_alphat;
        __syncthreads();
        for (int i = tid; i < CH*CH; i += 256) WT[(i & 63)*CH + (i >> 6)] = Wg[i];
        __syncthreads();
        float bb0 = bg[2*l], bb1 = bg[2*l + 1];
        #pragma unroll 1
        for (int i = 0; i < 8; i++) {
            int p = pbase + w * 8 + i;
            float a0 = bb0, a1 = bb1;
            const float4* fv4 = (const float4*)fbuf[w][i];
            #pragma unroll
            for (int c4 = 0; c4 < 16; c4++) {
                float4 fv = fv4[c4];
                float2 w0 = *(const float2*)&WT[(4*c4 + 0)*CH + 2*l];
                float2 w1 = *(const float2*)&WT[(4*c4 + 1)*CH + 2*l];
                float2 w2 = *(const float2*)&WT[(4*c4 + 2)*CH + 2*l];
                float2 w3 = *(const float2*)&WT[(4*c4 + 3)*CH + 2*l];
                a0 = fmaf(w0.x, fv.x, a0); a1 = fmaf(w0.y, fv.x, a1);
                a0 = fmaf(w1.x, fv.y, a0); a1 = fmaf(w1.y, fv.y, a1);
                a0 = fmaf(w2.x, fv.z, a0); a1 = fmaf(w2.y, fv.z, a1);
                a0 = fmaf(w3.x, fv.w, a0); a1 = fmaf(w3.y, fv.w, a1);
            }
            *(float2*)&og[p*CH + 2*l] = make_float2(a0, a1);
        }
    }
}

// ===== Kernel 2a: seed — exact fp32 16th-best over cands 0..SEEDN-1; zero cnt ====
__global__ void __launch_bounds__(128) seed_kernel() {
    __shared__ float sh[128*68];
    __shared__ float sqs[128];
    const int tid = threadIdx.x;
    const int b = blockIdx.x >> 5;
    const int qbase = (blockIdx.x & 31) * 256;
    const float* ft = g_ft + (size_t)b * NP * CH;

    ull qa[32], qb[32];
    load_q(ft, qbase + tid, qa);
    load_q(ft, qbase + tid + 128, qb);

    float bd0[16], bd1[16];
    #pragma unroll
    for (int t = 0; t < 16; t++) { bd0[t] = -3.0e38f; bd1[t] = -3.0e38f; }
    float thr0 = -3.0e38f, thr1 = -3.0e38f;
    int mp0 = 0, mp1 = 0;

    #pragma unroll 1
    for (int tb = 0; tb < SEEDN; tb += 128) {
        __syncthreads();
        const float4* src = (const float4*)(ft + (size_t)tb * CH);
        #pragma unroll
        for (int it = 0; it < 16; it++) {
            int i4 = tid + it * 128;
            int mi = i4 >> 4, c4 = i4 & 15;
            *(float4*)&sh[mi*68 + 4*c4] = src[i4];
        }
        sqs[tid] = g_sqn[b*NP + tb + tid];
        __syncthreads();

        #pragma unroll 1
        for (int mi = 0; mi < 128; mi++) {
            float e0, e1;
            dots2(qa, qb, &sh[mi*68], e0, e1);
            float sq = sqs[mi];
            float v0 = fmaf(2.f, e0, -sq);
            float v1 = fmaf(2.f, e1, -sq);
            if (v0 > thr0) {
                #pragma unroll
                for (int t = 0; t < 16; t++) if (t == mp0) bd0[t] = v0;
                float mn = bd0[0]; int mpos = 0;
                #pragma unroll
                for (int t = 1; t < 16; t++) if (bd0[t] < mn) { mn = bd0[t]; mpos = t; }
                thr0 = mn; mp0 = mpos;
            }
            if (v1 > thr1) {
                #pragma unroll
                for (int t = 0; t < 16; t++) if (t == mp1) bd1[t] = v1;
                float mn = bd1[0]; int mpos = 0;
                #pragma unroll
                for (int t = 1; t < 16; t++) if (bd1[t] < mn) { mn = bd1[t]; mpos = t; }
                thr1 = mn; mp1 = mpos;
            }
        }
    }
    int p0 = b*NP + qbase + tid, p1 = p0 + 128;
    g_tauf[p0] = thr0; g_cnt[p0] = 0;
    g_tauf[p1] = thr1; g_cnt[p1] = 0;
}

// ===== Kernel 2b: tf32 MMA distance tiles + threshold append (symmetric) =====
#define PUSH(KEY, TGT) do { \
    if (sp < SK) { stk[sp*256 + tid] = (KEY); stg[sp*256 + tid] = (TGT); sp++; } \
    else { int _pos = atomicAdd(&g_cnt[TGT], 1); \
           if (_pos < CAPK) g_bufk[(size_t)(TGT)*CAPK + _pos] = (KEY); } \
} while (0)

__global__ void __launch_bounds__(256, 2) mma_knn_kernel() {
    extern __shared__ char dynsm[];
    uint*  smi = (uint*)dynsm;
    uint*  smj = smi + 128*68;
    ull*   stk = (ull*)(smj + 128*68);
    int*   stg = (int*)(stk + SK*256);
    float* sqi = (float*)(stg + SK*256);
    float* sqj = sqi + 128;
    float* tti = sqj + 128;
    float* ttj = tti + 128;

    const int tid = threadIdx.x;
    int tb = blockIdx.x;
    const int b = tb / 2080;
    int r = tb - b * 2080;
    int ci = 0;
    while (r >= 64 - ci) { r -= 64 - ci; ci++; }
    const int cj = ci + r;
    const bool offd = (ci != cj);
    const int qch = ci * 128, cch = cj * 128;
    const int bNP = b * NP;
    const uint* ftf = g_fttf + (size_t)bNP * CH;

    #pragma unroll
    for (int it = 0; it < 8; it++) {
        int i4 = tid + it * 256;
        int row = i4 >> 4, c4 = i4 & 15;
        *(uint4*)&smi[row*68 + c4*4] = *(const uint4*)&ftf[(size_t)(qch + row)*CH + c4*4];
        *(uint4*)&smj[row*68 + c4*4] = *(const uint4*)&ftf[(size_t)(cch + row)*CH + c4*4];
    }
    if (tid < 128) {
        sqi[tid] = g_sqn[bNP + qch + tid];
        sqj[tid] = g_sqn[bNP + cch + tid];
        tti[tid] = g_tauf[bNP + qch + tid] - EPS_MAIN;
        ttj[tid] = g_tauf[bNP + cch + tid] - EPS_MAIN;
    }
    __syncthreads();

    const int w = tid >> 5, t = tid & 31, ty = t >> 2, tx = t & 3;
    float acc[64];
    #pragma unroll
    for (int z = 0; z < 64; z++) acc[z] = 0.f;
    const int arow0 = (w*16 + ty)*68, arow1 = arow0 + 8*68;

    #pragma unroll
    for (int ks = 0; ks < 8; ks++) {
        int ko = ks*8 + tx;
        uint a0 = smi[arow0 + ko],     a1 = smi[arow1 + ko];
        uint a2 = smi[arow0 + ko + 4], a3 = smi[arow1 + ko + 4];
        #pragma unroll
        for (int nt = 0; nt < 16; nt++) {
            int boff = (nt*8 + ty)*68 + ko;
            mma_tf32(acc + nt*4, a0, a1, a2, a3, smj[boff], smj[boff + 4]);
        }
    }

    int sp = 0;
    const int lr0 = w*16 + ty, lr1 = lr0 + 8;
    const float sq0 = sqi[lr0], sq1 = sqi[lr1];
    const float tt0 = tti[lr0], tt1 = tti[lr1];
    const int pq0 = bNP + qch + lr0, pq1 = pq0 + 8;
    const int gq0 = qch + lr0, gq1 = gq0 + 8;

    #pragma unroll
    for (int nt = 0; nt < 16; nt++) {
        int lc0 = nt*8 + tx*2, lc1 = lc0 + 1;
        float sj0 = sqj[lc0], sj1 = sqj[lc1];
        int gm0 = cch + lc0, gm1 = cch + lc1;
        float a0v = acc[4*nt], a1v = acc[4*nt+1], a2v = acc[4*nt+2], a3v = acc[4*nt+3];
        float s;
        s = fmaf(2.f, a0v, -sj0); if (s >= tt0) PUSH(skey(s, gm0), pq0);
        s = fmaf(2.f, a1v, -sj1); if (s >= tt0) PUSH(skey(s, gm1), pq0);
        s = fmaf(2.f, a2v, -sj0); if (s >= tt1) PUSH(skey(s, gm0), pq1);
        s = fmaf(2.f, a3v, -sj1); if (s >= tt1) PUSH(skey(s, gm1), pq1);
        if (offd) {
            float tj0 = ttj[lc0], tj1 = ttj[lc1];
            int pm0 = bNP + gm0, pm1 = bNP + gm1;
            s = fmaf(2.f, a0v, -sq0); if (s >= tj0) PUSH(skey(s, gq0), pm0);
            s = fmaf(2.f, a1v, -sq0); if (s >= tj1) PUSH(skey(s, gq0), pm1);
            s = fmaf(2.f, a2v, -sq1); if (s >= tj0) PUSH(skey(s, gq1), pm0);
            s = fmaf(2.f, a3v, -sq1); if (s >= tj1) PUSH(skey(s, gq1), pm1);
        }
    }

    {
        int posv[SK];
        #pragma unroll
        for (int k = 0; k < SK; k++)
            posv[k] = (k < sp) ? atomicAdd(&g_cnt[stg[k*256 + tid]], 1) : 0;
        #pragma unroll
        for (int k = 0; k < SK; k++) if (k < sp) {
            int pos = posv[k];
            if (pos < CAPK) g_bufk[(size_t)stg[k*256 + tid]*CAPK + pos] = stk[k*256 + tid];
        }
    }
}

// ===== Kernel 2c: select — warp/query: approx scan + extraction + coop rescore ===
__global__ void __launch_bounds__(256) select_kernel() {
    const int lane = threadIdx.x & 31;
    const int p = blockIdx.x * 8 + (threadIdx.x >> 5);
    const int b = p >> 13;
    const int bNP = b * NP;
    int n = g_cnt[p]; if (n > CAPK) n = CAPK;

    const ull* row = g_bufk + (size_t)p * CAPK;
    const float2 q2 = *(const float2*)(g_ft + (size_t)p * CH + 2*lane);

    // Phase 1: lane-local approx top-16 over lane-strided (coalesced) keys
    ull bk[16];
    #pragma unroll
    for (int t = 0; t < 16; t++) bk[t] = 0ull;
    ull thrk = 0ull; int mp = 0;
    #pragma unroll 1
    for (int e = lane; e < n; e += 32) {
        ull k = row[e];
        if (k > thrk) {
            #pragma unroll
            for (int t = 0; t < 16; t++) if (t == mp) bk[t] = k;
            ull mn = bk[0]; int mpos = 0;
            #pragma unroll
            for (int t = 1; t < 16; t++) if (bk[t] < mn) { mn = bk[t]; mpos = t; }
            thrk = mn; mp = mpos;
        }
    }

    // Phase 2: 16 warp-max extraction rounds -> approx 16th value
    ull gm16 = 0ull;
    #pragma unroll 1
    for (int r = 0; r < 16; r++) {
        ull lm = bk[0]; int lp = 0;
        #pragma unroll
        for (int t = 1; t < 16; t++) if (bk[t] > lm) { lm = bk[t]; lp = t; }
        ull gm = lm;
        #pragma unroll
        for (int off = 16; off; off >>= 1) {
            ull o = __shfl_xor_sync(0xffffffffu, gm, off);
            if (o > gm) gm = o;
        }
        if (lm == gm && gm != 0ull) {
            #pragma unroll
            for (int t = 0; t < 16; t++) if (t == lp) bk[t] = 0ull;
        }
        gm16 = gm;
    }
    const float thr_val = keyval(gm16) - EPS_SEL;

    // Phase 3: rescan; ballot survivors; cooperative exact rescore (warp-uniform)
    #pragma unroll
    for (int t = 0; t < 16; t++) bk[t] = 0ull;
    thrk = 0ull; mp = 0;

    #pragma unroll 1
    for (int base = 0; base < n; base += 32) {
        int e = base + lane;
        ull k = (e < n) ? row[e] : 0ull;
        bool surv = (e < n) && (keyval(k) >= thr_val);
        uint mask = __ballot_sync(0xffffffffu, surv);
        while (mask) {
            int src = __ffs(mask) - 1;
            mask &= mask - 1;
            ull ks = __shfl_sync(0xffffffffu, k, src);
            int m = (int)~(uint)ks;
            float2 c2 = *(const float2*)(g_ft + (size_t)(bNP + m)*CH + 2*lane);
            float s = fmaf(q2.x, c2.x, q2.y * c2.y);
            #pragma unroll
            for (int off = 16; off; off >>= 1)
                s += __shfl_xor_sync(0xffffffffu, s, off);
            float v = fmaf(2.f, s, -g_sqn[bNP + m]);
            ull k2 = skey(v, m);
            if (k2 > thrk) {
                #pragma unroll
                for (int t = 0; t < 16; t++) if (t == mp) bk[t] = k2;
                ull mn = bk[0]; int mpos = 0;
                #pragma unroll
                for (int t = 1; t < 16; t++) if (bk[t] < mn) { mn = bk[t]; mpos = t; }
                thrk = mn; mp = mpos;
            }
        }
    }

    if (lane == 0) {
        int* dst = g_knn + (size_t)p * KK;
        #pragma unroll
        for (int t = 0; t < 16; t++) dst[t] = (int)~(uint)bk[t];
    }
}

// ===== Kernel 3: per-neighbor MLP + softmax =====
__global__ void __launch_bounds__(128) agg_kernel(
    const float* __restrict__ Wd1, const float* __restrict__ bd1,
    const float* __restrict__ bd2, const float* __restrict__ bg1,
    const float* __restrict__ bg2, float* __restrict__ out)
{
    __shared__ float bufA[4][CH * 20];
    __shared__ float bufB[4][CH * 20];
    __shared__ float cds[4][48];
    __shared__ int   idxs[4][16];

    const int w = threadIdx.x >> 5, l = threadIdx.x & 31;
    const int r0 = 2 * l, r1 = 2 * l + 1;

    const float w00 = Wd1[r0*3+0], w01 = Wd1[r0*3+1], w02 = Wd1[r0*3+2];
    const float w10 = Wd1[r1*3+0], w11 = Wd1[r1*3+1], w12 = Wd1[r1*3+2];
    const float bd1_0 = bd1[r0], bd1_1 = bd1[r1];
    const float bd2_0 = bd2[r0], bd2_1 = bd2[r1];
    const float bg1_0 = bg1[r0], bg1_1 = bg1[r1];
    const float bg2_0 = bg2[r0], bg2_1 = bg2[r1];

    #pragma unroll 1
    for (int i = 0; i < 8; i++) {
        const int p = (blockIdx.x * 4 + w) * 8 + i;
        const int b = p >> 13, n = p & (NP - 1);

        if (l < 16) {
            int m = g_knn[p * KK + l];
            idxs[w][l] = m;
            const float* cn = g_coordst + p * 3;
            const float* cm = g_coordst + (b * NP + m) * 3;
            cds[w][l]      = cn[0] - cm[0];
            cds[w][16 + l] = cn[1] - cm[1];
            cds[w][32 + l] = cn[2] - cm[2];
        }
        __syncwarp();

        #pragma unroll
        for (int k = 0; k < 16; k++) {
            float c0 = cds[w][k], c1 = cds[w][16 + k], c2 = cds[w][32 + k];
            float h0 = fmaxf(fmaf(w02, c2, fmaf(w01, c1, fmaf(w00, c0, bd1_0))), 0.f);
            float h1 = fmaxf(fmaf(w12, c2, fmaf(w11, c1, fmaf(w10, c0, bd1_1))), 0.f);
            bufA[w][r0*20 + k] = h0;
            bufA[w][r1*20 + k] = h1;
        }
        __syncwarp();

        ull D0[8], D1[8];
        {
            ull b0 = pack2(bd2_0, bd2_0), b1 = pack2(bd2_1, bd2_1);
            #pragma unroll
            for (int jj = 0; jj < 8; jj++) { D0[jj] = b0; D1[jj] = b1; }
        }
        #pragma unroll 4
        for (int c = 0; c < CH; c++) {
            float2 wv = *(const float2*)&g_WTd2[c*CH + r0];
            ull wx = pack2(wv.x, wv.x), wy = pack2(wv.y, wv.y);
            const ulonglong2* hr = (const ulonglong2*)&bufA[w][c*20];
            #pragma unroll
            for (int jj = 0; jj < 4; jj++) {
                ulonglong2 h2 = hr[jj];
                FMA2(D0[2*jj], wx, h2.x); FMA2(D0[2*jj+1], wx, h2.y);
                FMA2(D1[2*jj], wy, h2.x); FMA2(D1[2*jj+1], wy, h2.y);
            }
        }
        float d0[16], d1[16];
        #pragma unroll
        for (int jj = 0; jj < 8; jj++) {
            float2 u = unpack2(D0[jj]); d0[2*jj] = u.x; d0[2*jj+1] = u.y;
            float2 v = unpack2(D1[jj]); d1[2*jj] = v.x; d1[2*jj+1] = v.y;
        }
        __syncwarp();

        {
            float2 ph = *(const float2*)&g_phit[p*CH + r0];
            #pragma unroll
            for (int k = 0; k < 16; k++) {
                int m = idxs[w][k];
                float2 ps = *(const float2*)&g_psit[(size_t)(b*NP + m)*CH + r0];
                bufA[w][r0*20 + k] = ph.x - ps.x + d0[k];
                bufA[w][r1*20 + k] = ph.y - ps.y + d1[k];
            }
        }
        __syncwarp();

        {
            ull G0[8], G1[8];
            {
                ull b0 = pack2(bg1_0, bg1_0), b1 = pack2(bg1_1, bg1_1);
                #pragma unroll
                for (int jj = 0; jj < 8; jj++) { G0[jj] = b0; G1[jj] = b1; }
            }
            #pragma unroll 4
            for (int c = 0; c < CH; c++) {
                float2 wv = *(const float2*)&g_WTg1[c*CH + r0];
                ull wx = pack2(wv.x, wv.x), wy = pack2(wv.y, wv.y);
                const ulonglong2* xr = (const ulonglong2*)&bufA[w][c*20];
                #pragma unroll
                for (int jj = 0; jj < 4; jj++) {
                    ulonglong2 x2 = xr[jj];
                    FMA2(G0[2*jj], wx, x2.x); FMA2(G0[2*jj+1], wx, x2.y);
                    FMA2(G1[2*jj], wy, x2.x); FMA2(G1[2*jj+1], wy, x2.y);
                }
            }
            #pragma unroll
            for (int jj = 0; jj < 8; jj++) {
                float2 u = unpack2(G0[jj]);
                bufB[w][r0*20 + 2*jj]     = fmaxf(u.x, 0.f);
                bufB[w][r0*20 + 2*jj + 1] = fmaxf(u.y, 0.f);
                float2 v = unpack2(G1[jj]);
                bufB[w][r1*20 + 2*jj]     = fmaxf(v.x, 0.f);
                bufB[w][r1*20 + 2*jj + 1] = fmaxf(v.y, 0.f);
            }
        }
        __syncwarp();

        float gm0[16], gm1[16];
        {
            ull M0[8], M1[8];
            {
                ull b0 = pack2(bg2_0, bg2_0), b1 = pack2(bg2_1, bg2_1);
                #pragma unroll
                for (int jj = 0; jj < 8; jj++) { M0[jj] = b0; M1[jj] = b1; }
            }
            #pragma unroll 4
            for (int c = 0; c < CH; c++) {
                float2 wv = *(const float2*)&g_WTg2[c*CH + r0];
                ull wx = pack2(wv.x, wv.x), wy = pack2(wv.y, wv.y);
                const ulonglong2* gr = (const ulonglong2*)&bufB[w][c*20];
                #pragma unroll
                for (int jj = 0; jj < 4; jj++) {
                    ulonglong2 g2 = gr[jj];
                    FMA2(M0[2*jj], wx, g2.x); FMA2(M0[2*jj+1], wx, g2.y);
                    FMA2(M1[2*jj], wy, g2.x); FMA2(M1[2*jj+1], wy, g2.y);
                }
            }
            #pragma unroll
            for (int jj = 0; jj < 8; jj++) {
                float2 u = unpack2(M0[jj]); gm0[2*jj] = u.x; gm0[2*jj+1] = u.y;
                float2 v = unpack2(M1[jj]); gm1[2*jj] = v.x; gm1[2*jj+1] = v.y;
            }
        }

        {
            float mx0 = gm0[0], mx1 = gm1[0];
            #pragma unroll
            for (int k = 1; k < 16; k++) { mx0 = fmaxf(mx0, gm0[k]); mx1 = fmaxf(mx1, gm1[k]); }
            float s0 = 0.f, s1 = 0.f;
            #pragma unroll
            for (int k = 0; k < 16; k++) {
                gm0[k] = __expf(gm0[k] - mx0); s0 += gm0[k];
                gm1[k] = __expf(gm1[k] - mx1); s1 += gm1[k];
            }
            float2 al = *(const float2*)&g_alphat[p*CH + r0];
            float acc0 = 0.f, acc1 = 0.f;
            #pragma unroll
            for (int k = 0; k < 16; k++) {
                acc0 = fmaf(gm0[k], al.x + d0[k], acc0);
                acc1 = fmaf(gm1[k], al.y + d1[k], acc1);
            }
            out[(size_t)b*CH*NP + (size_t)r0*NP + n] = acc0 / s0;
            out[(size_t)b*CH*NP + (size_t)r1*NP + n] = acc1 / s1;
        }
        __syncwarp();
    }
}

extern "C" void kernel_launch(void* const* d_in, const int* in_sizes, int n_in,
                              void* d_out, int out_size) {
    const float* features = (const float*)d_in[0];
    const float* coords   = (const float*)d_in[1];

    const int mma_smem = 2*128*68*4 + SK*256*8 + SK*256*4 + 4*128*4;  // 102400 B
    static int attr_done = 0;
    if (!attr_done) {
        cudaFuncSetAttribute(mma_knn_kernel, cudaFuncAttributeMaxDynamicSharedMemorySize, mma_smem);
        attr_done = 1;
    }

    proj_kernel<<<512, 256>>>(features, coords,
        (const float*)d_in[2], (const float*)d_in[3],
        (const float*)d_in[4], (const float*)d_in[5],
        (const float*)d_in[6], (const float*)d_in[7],
        (const float*)d_in[8], (const float*)d_in[10],
        (const float*)d_in[14]);
    seed_kernel<<<128, 128>>>();
    mma_knn_kernel<<<4*2080, 256, mma_smem>>>();
    select_kernel<<<TOT/8, 256>>>();
    agg_kernel<<<1024, 128>>>(
        (const float*)d_in[12], (const float*)d_in[13],
        (const float*)d_in[15], (const float*)d_in[9],
        (const float*)d_in[11], (float*)d_out);
}